// round 15
// baseline (speedup 1.0000x reference)
#include <cuda_runtime.h>
#include <cuda_bf16.h>
#include <cstdint>

// ---------------- problem constants ----------------
#define NUM_CHARS 128
#define UNITS     256
#define BATCH     512
#define SEQ       1024

// ---------------- decomposition ----------------
#define NCLUST  8      // clusters
#define CPG     8      // CTAs per cluster
#define MBATCH  64     // batch rows per cluster/CTA (2 n-groups of 32)
#define UC      32     // units per CTA
#define KDIM    256
#define NCTAS   (NCLUST*CPG)   // 64
#define NTHREADS 256   // 8 warps: 4 m-groups x 2 n-halves (per n-group)

// ---------------- smem layout ----------------
#define OFF_AHI    1024                      // W_hi [128 m][256 k] bf16 swizzled = 64KB
#define OFF_ALO    (OFF_AHI + 65536)         // W_lo                              = 64KB
#define OFF_BHI    (OFF_ALO + 65536)         // h_hi [64 n][256 k] bf16 swizzled  = 32KB
#define OFF_BLO    (OFF_BHI + 32768)         // h_lo                              = 32KB
#define SMEM_TOTAL (OFF_BLO + 32768)         // 197632 B

__device__ unsigned g_h[2][BATCH * UNITS];   // packed (bf16 hi | bf16 lo << 16)

// ---------------- helpers ----------------
__device__ __forceinline__ uint32_t smem_u32(const void* p) {
    uint32_t a;
    asm("{ .reg .u64 t; cvta.to.shared.u64 t, %1; cvt.u32.u64 %0, t; }" : "=r"(a) : "l"(p));
    return a;
}
#define CLUSTER_ARRIVE() asm volatile("barrier.cluster.arrive.aligned;" ::: "memory")
#define CLUSTER_WAIT()   asm volatile("barrier.cluster.wait.aligned;" ::: "memory")

__device__ __forceinline__ uint32_t swz(int row, int k) {
    return (uint32_t)row * 512u
         + (((((uint32_t)k >> 3) << 4)) ^ (((uint32_t)row & 7u) << 4))
         + (((uint32_t)k & 7u) << 1);
}

__device__ __forceinline__ void ldsm_x4(uint32_t r[4], uint32_t addr) {
    asm volatile("ldmatrix.sync.aligned.m8n8.x4.shared.b16 {%0,%1,%2,%3}, [%4];"
                 : "=r"(r[0]), "=r"(r[1]), "=r"(r[2]), "=r"(r[3]) : "r"(addr));
}

__device__ __forceinline__ void mma_bf16(float c[4],
                                         uint32_t a0, uint32_t a1, uint32_t a2, uint32_t a3,
                                         uint32_t b0, uint32_t b1) {
    asm volatile("mma.sync.aligned.m16n8k16.row.col.f32.bf16.bf16.f32 "
                 "{%0,%1,%2,%3}, {%4,%5,%6,%7}, {%8,%9}, {%0,%1,%2,%3};"
                 : "+f"(c[0]), "+f"(c[1]), "+f"(c[2]), "+f"(c[3])
                 : "r"(a0), "r"(a1), "r"(a2), "r"(a3), "r"(b0), "r"(b1));
}

__device__ __forceinline__ uint32_t prmt(uint32_t a, uint32_t b, uint32_t sel) {
    uint32_t d;
    asm("prmt.b32 %0, %1, %2, %3;" : "=r"(d) : "r"(a), "r"(b), "r"(sel));
    return d;
}

// fast activations: explicit MUFU
__device__ __forceinline__ float ex2f(float x) { float y; asm("ex2.approx.ftz.f32 %0, %1;" : "=f"(y) : "f"(x)); return y; }
__device__ __forceinline__ float rcpf(float x) { float y; asm("rcp.approx.ftz.f32 %0, %1;" : "=f"(y) : "f"(x)); return y; }
#define LOG2E 1.4426950408889634f
__device__ __forceinline__ float sigm(float x) { return rcpf(1.0f + ex2f(-LOG2E * x)); }
__device__ __forceinline__ float tanh_fast(float x) { return 1.0f - 2.0f * rcpf(ex2f(2.0f * LOG2E * x) + 1.0f); }

__global__ void init_kernel() {
    int i = blockIdx.x * blockDim.x + threadIdx.x;
    for (; i < BATCH * UNITS; i += gridDim.x * blockDim.x) g_h[0][i] = 0u;
}

// ---------------- main persistent kernel ----------------
__global__ void __launch_bounds__(NTHREADS, 1) __cluster_dims__(CPG, 1, 1)
lstm_kernel(const int* __restrict__ tokens,
            const float* __restrict__ Wx,
            const float* __restrict__ Wh,
            const float* __restrict__ bias,
            const float* __restrict__ Wd,
            const float* __restrict__ bd,
            float* __restrict__ out) {
    extern __shared__ __align__(1024) char smem[];
    const uint32_t sb = smem_u32(smem);
    const int tid = threadIdx.x;
    const int w   = tid >> 5;
    const int L   = tid & 31;
    const int mg  = w & 3;               // m-group (32 A-rows)
    const int nh  = w >> 2;              // n-half within each 32-row n-group
    const int cl  = blockIdx.x >> 3;     // cluster 0..7
    const int r   = blockIdx.x & 7;      // rank
    const int gbase = cl * MBATCH;       // 64 batch rows per cluster

    // ---- prologue: W_h (fp32 -> bf16 hi/lo) ----
    {
        const int m  = tid & 127;
        const int kh = tid >> 7;
        const int rw = m & 31;
        const int gate = rw >> 3;
        const int ulocal = (m >> 5) * 8 + (rw & 7);
        const int col = gate * 256 + r * UC + ulocal;
        for (int k = kh * 128; k < kh * 128 + 128; k++) {
            float wv = Wh[k * 1024 + col];
            __nv_bfloat16 hi = __float2bfloat16(wv);
            float rem = wv - __bfloat162float(hi);
            __nv_bfloat16 lo = __float2bfloat16(rem);
            uint32_t s = swz(m, k);
            *(__nv_bfloat16*)(smem + OFF_AHI + s) = hi;
            *(__nv_bfloat16*)(smem + OFF_ALO + s) = lo;
        }
    }

    // per-lane owned unit + bias regs; Wx row bases (GLOBAL — gathered in skew shadow)
    const int ul = mg * 8 + (L >> 2);
    const int colbase = r * UC + ul;
    const float bi = bias[0 * 256 + colbase];
    const float bj = bias[1 * 256 + colbase];
    const float bf = bias[2 * 256 + colbase];
    const float bo = bias[3 * 256 + colbase];

    // ---- ldmatrix addresses ----
    const int rA   = (L & 7) + 8 * ((L >> 3) & 1);
    const uint32_t koffA = (L >> 4) ? 16u : 0u;
    const int rowA0 = mg * 32 + rA;
    const int rowA1 = rowA0 + 16;
    const uint32_t xA = ((uint32_t)rowA0 & 7u) << 4;
    const uint32_t aHi0 = sb + OFF_AHI + rowA0 * 512u;
    const uint32_t aHi1 = sb + OFF_AHI + rowA1 * 512u;
    const uint32_t aLo0 = sb + OFF_ALO + rowA0 * 512u;
    const uint32_t aLo1 = sb + OFF_ALO + rowA1 * 512u;
    const int rB = L & 7;
    const uint32_t koffB = ((L >> 3) & 1) ? 16u : 0u;
    const int nBl = nh * 16 + ((L >> 4) & 1) * 8 + rB;   // row within a 32-row n-group
    const uint32_t xB = ((uint32_t)rB & 7u) << 4;
    // per n-group B bases
    uint32_t bHiG[2], bLoG[2];
#pragma unroll
    for (int gg = 0; gg < 2; gg++) {
        bHiG[gg] = sb + OFF_BHI + (gg * 32 + nBl) * 512u;
        bLoG[gg] = sb + OFF_BLO + (gg * 32 + nBl) * 512u;
    }

    // per-lane batch cols + global h indices, per n-group
    int gidx[2][4];
    int brow[2][4];
#pragma unroll
    for (int gg = 0; gg < 2; gg++)
#pragma unroll
        for (int nb = 0; nb < 2; nb++)
#pragma unroll
            for (int j = 0; j < 2; j++) {
                int colb = nh * 16 + nb * 8 + (L & 3) * 2 + j;
                int row = gbase + gg * 32 + colb;
                brow[gg][nb * 2 + j] = row;
                gidx[gg][nb * 2 + j] = row * UNITS + colbase;
            }

    float c_reg[2][4];
#pragma unroll
    for (int gg = 0; gg < 2; gg++)
#pragma unroll
        for (int k = 0; k < 4; k++) c_reg[gg][k] = 0.0f;

    __syncthreads();

    // ---- A_hi m-tile0 register-stationary ----
    uint32_t AH0[16][4];
#pragma unroll
    for (int ks = 0; ks < 16; ks++) {
        const uint32_t ka = ((uint32_t)(ks * 32) + koffA) ^ xA;
        ldsm_x4(AH0[ks], aHi0 + ka);
    }

    CLUSTER_ARRIVE();

    // t=0 prefetch: tokens + Wx rows (global; L2-resident)
    float wvi[2][4], wvj[2][4], wvf[2][4], wvo[2][4];
#pragma unroll
    for (int gg = 0; gg < 2; gg++)
#pragma unroll
        for (int e = 0; e < 4; e++) {
            int tk = __ldg(&tokens[brow[gg][e] * SEQ + 0]);
            const float* wxb = &Wx[tk * 1024 + colbase];
            wvi[gg][e] = __ldg(wxb);
            wvj[gg][e] = __ldg(wxb + 256);
            wvf[gg][e] = __ldg(wxb + 512);
            wvo[gg][e] = __ldg(wxb + 768);
        }

    // ---- 1024 recurrent steps ----
    for (int t = 0; t < SEQ; t++) {
        CLUSTER_WAIT();   // all CTAs' h(t) stores visible; CTA-wide barrier

        // fill B: 64 rows x 256 k (4096 uint4), unpack packed bf16 pairs
        {
            const uint4* src = (const uint4*)&g_h[t & 1][gbase * UNITS];
#pragma unroll
            for (int ii = 0; ii < 16; ii++) {
                int idx4 = tid + (ii << 8);
                uint4 p = __ldcg(src + idx4);
                int n  = idx4 >> 6;
                int k4 = (idx4 & 63) << 2;
                uint32_t s = swz(n, k4);
                *(uint2*)(smem + OFF_BHI + s) = make_uint2(prmt(p.x, p.y, 0x5410u), prmt(p.z, p.w, 0x5410u));
                *(uint2*)(smem + OFF_BLO + s) = make_uint2(prmt(p.x, p.y, 0x7632u), prmt(p.z, p.w, 0x7632u));
            }
        }
        __syncthreads();

        unsigned* dst = &g_h[(t + 1) & 1][0];

        // ---- two n-groups sequentially (one barrier per step amortized over both) ----
#pragma unroll
        for (int gg = 0; gg < 2; gg++) {
            const uint32_t bHi = bHiG[gg];
            const uint32_t bLo = bLoG[gg];

            float acc[2][2][4];
#pragma unroll
            for (int mt = 0; mt < 2; mt++)
#pragma unroll
                for (int nb = 0; nb < 2; nb++)
#pragma unroll
                    for (int e = 0; e < 4; e++) acc[mt][nb][e] = 0.0f;

#pragma unroll
            for (int ks = 0; ks < 16; ks++) {
                const uint32_t ka = ((uint32_t)(ks * 32) + koffA) ^ xA;
                const uint32_t kb = ((uint32_t)(ks * 32) + koffB) ^ xB;
                uint32_t Ah1[4], Al0[4], Al1[4], Bh[4], Bl[4];
                ldsm_x4(Bh, bHi + kb);
                ldsm_x4(Ah1, aHi1 + ka);
                ldsm_x4(Al0, aLo0 + ka);
                ldsm_x4(Al1, aLo1 + ka);
                ldsm_x4(Bl, bLo + kb);
#pragma unroll
                for (int nb = 0; nb < 2; nb++) {
                    mma_bf16(acc[0][nb], AH0[ks][0], AH0[ks][1], AH0[ks][2], AH0[ks][3], Bh[2 * nb], Bh[2 * nb + 1]);
                    mma_bf16(acc[1][nb], Ah1[0], Ah1[1], Ah1[2], Ah1[3], Bh[2 * nb], Bh[2 * nb + 1]);
                    mma_bf16(acc[0][nb], Al0[0], Al0[1], Al0[2], Al0[3], Bh[2 * nb], Bh[2 * nb + 1]);
                    mma_bf16(acc[1][nb], Al1[0], Al1[1], Al1[2], Al1[3], Bh[2 * nb], Bh[2 * nb + 1]);
                    mma_bf16(acc[0][nb], AH0[ks][0], AH0[ks][1], AH0[ks][2], AH0[ks][3], Bl[2 * nb], Bl[2 * nb + 1]);
                    mma_bf16(acc[1][nb], Ah1[0], Ah1[1], Ah1[2], Ah1[3], Bl[2 * nb], Bl[2 * nb + 1]);
                }
            }

            // LSTM elementwise in registers; store h(t+1)
#pragma unroll
            for (int nb = 0; nb < 2; nb++) {
#pragma unroll
                for (int j = 0; j < 2; j++) {
                    const int e = nb * 2 + j;
                    float gi = acc[0][nb][j]     + wvi[gg][e] + bi;
                    float gj = acc[0][nb][2 + j] + wvj[gg][e] + bj;
                    float gf = acc[1][nb][j]     + wvf[gg][e] + bf;
                    float go = acc[1][nb][2 + j] + wvo[gg][e] + bo;
                    float nc = c_reg[gg][e] * sigm(gf + 1.0f) + sigm(gi) * tanh_fast(gj);
                    c_reg[gg][e] = nc;
                    float nh2 = tanh_fast(nc) * sigm(go);
                    __nv_bfloat16 hi = __float2bfloat16(nh2);
                    float rem = nh2 - __bfloat162float(hi);
                    __nv_bfloat16 lo = __float2bfloat16(rem);
                    unsigned packed = (unsigned)__bfloat16_as_ushort(hi) | ((unsigned)__bfloat16_as_ushort(lo) << 16);
                    __stcg(&dst[gidx[gg][e]], packed);
                }
            }
        }
        CLUSTER_ARRIVE();   // h(t+1) stores ordered (release)

        // prefetch next tokens + Wx rows in the skew shadow (global, L2-resident)
        {
            const int tp = (t + 1 < SEQ) ? (t + 1) : (SEQ - 1);
#pragma unroll
            for (int gg = 0; gg < 2; gg++)
#pragma unroll
                for (int e = 0; e < 4; e++) {
                    int tk = __ldg(&tokens[brow[gg][e] * SEQ + tp]);
                    const float* wxb = &Wx[tk * 1024 + colbase];
                    wvi[gg][e] = __ldg(wxb);
                    wvj[gg][e] = __ldg(wxb + 256);
                    wvf[gg][e] = __ldg(wxb + 512);
                    wvo[gg][e] = __ldg(wxb + 768);
                }
        }
    }

    // ---- dense head: logits = h @ W_dense + b_dense (final h in g_h[0]) ----
    CLUSTER_WAIT();
    {
        float* hs = (float*)(smem + OFF_AHI);   // 8 rows x 256 fp32 = 8KB
        const int bstart = r * 8;               // 8 batch rows per CTA
        for (int i = tid; i < 8 * UNITS; i += NTHREADS) {
            unsigned p = __ldcg(&g_h[0][(gbase + bstart + (i >> 8)) * UNITS + (i & 255)]);
            hs[i] = __bfloat162float(__ushort_as_bfloat16((unsigned short)(p & 0xFFFFu))) +
                    __bfloat162float(__ushort_as_bfloat16((unsigned short)(p >> 16)));
        }
        __syncthreads();
        const int n  = tid & 127;   // output char
        const int pr = tid >> 7;    // 4 batch rows each
        float a0 = bd[n], a1 = bd[n], a2 = bd[n], a3 = bd[n];
        for (int k = 0; k < UNITS; k++) {
            float wv = Wd[k * NUM_CHARS + n];
            a0 += hs[(pr * 4 + 0) * 256 + k] * wv;
            a1 += hs[(pr * 4 + 1) * 256 + k] * wv;
            a2 += hs[(pr * 4 + 2) * 256 + k] * wv;
            a3 += hs[(pr * 4 + 3) * 256 + k] * wv;
        }
        out[(gbase + bstart + pr * 4 + 0) * NUM_CHARS + n] = a0;
        out[(gbase + bstart + pr * 4 + 1) * NUM_CHARS + n] = a1;
        out[(gbase + bstart + pr * 4 + 2) * NUM_CHARS + n] = a2;
        out[(gbase + bstart + pr * 4 + 3) * NUM_CHARS + n] = a3;
    }
}

// ---------------- host launcher ----------------
extern "C" void kernel_launch(void* const* d_in, const int* in_sizes, int n_in,
                              void* d_out, int out_size) {
    (void)in_sizes; (void)n_in; (void)out_size;
    const int*   tokens = (const int*)d_in[0];
    const float* Wx     = (const float*)d_in[1];
    const float* Wh     = (const float*)d_in[2];
    const float* b      = (const float*)d_in[3];
    const float* Wd     = (const float*)d_in[4];
    const float* bdn    = (const float*)d_in[5];
    float* out = (float*)d_out;

    cudaFuncSetAttribute(lstm_kernel, cudaFuncAttributeMaxDynamicSharedMemorySize, SMEM_TOTAL);

    init_kernel<<<256, 256>>>();
    lstm_kernel<<<NCTAS, NTHREADS, SMEM_TOTAL>>>(tokens, Wx, Wh, b, Wd, bdn, out);
}

// round 16
// speedup vs baseline: 1.5757x; 1.5757x over previous
#include <cuda_runtime.h>
#include <cuda_bf16.h>
#include <cstdint>

// ---------------- problem constants ----------------
#define NUM_CHARS 128
#define UNITS     256
#define BATCH     512
#define SEQ       1024

// ---------------- decomposition ----------------
#define GROUPS 16
#define CPG    8
#define MBATCH 32
#define UC     32
#define KDIM   256
#define NCTAS  (GROUPS*CPG)
#define NTHREADS 512   // 16 warps: 4 m-groups x 4 n-quarters -> 4 warps per SMSP scheduler

// ---------------- smem layout ----------------
#define OFF_AHI    1024                     // W_hi [128 m][256 k] bf16 swizzled = 64KB
#define OFF_ALO    (OFF_AHI + 65536)        // W_lo                              = 64KB
#define OFF_BHI    (OFF_ALO + 65536)        // h_hi [32 n][256 k] bf16 swizzled  = 16KB
#define OFF_BLO    (OFF_BHI + 16384)        // h_lo                              = 16KB
#define OFF_WX     (OFF_BLO + 16384)        // Wx fp32 [128 m][130 ch]           = 66560B
#define SMEM_TOTAL (OFF_WX + 66560)

__device__ unsigned g_h[2][BATCH * UNITS];   // packed (bf16 hi | bf16 lo << 16)

// ---------------- helpers ----------------
__device__ __forceinline__ uint32_t smem_u32(const void* p) {
    uint32_t a;
    asm("{ .reg .u64 t; cvta.to.shared.u64 t, %1; cvt.u32.u64 %0, t; }" : "=r"(a) : "l"(p));
    return a;
}
#define CLUSTER_ARRIVE() asm volatile("barrier.cluster.arrive.aligned;" ::: "memory")
#define CLUSTER_WAIT()   asm volatile("barrier.cluster.wait.aligned;" ::: "memory")

__device__ __forceinline__ uint32_t swz(int row, int k) {
    return (uint32_t)row * 512u
         + (((((uint32_t)k >> 3) << 4)) ^ (((uint32_t)row & 7u) << 4))
         + (((uint32_t)k & 7u) << 1);
}

__device__ __forceinline__ void ldsm_x4(uint32_t r[4], uint32_t addr) {
    asm volatile("ldmatrix.sync.aligned.m8n8.x4.shared.b16 {%0,%1,%2,%3}, [%4];"
                 : "=r"(r[0]), "=r"(r[1]), "=r"(r[2]), "=r"(r[3]) : "r"(addr));
}
__device__ __forceinline__ void ldsm_x2(uint32_t r[2], uint32_t addr) {
    asm volatile("ldmatrix.sync.aligned.m8n8.x2.shared.b16 {%0,%1}, [%2];"
                 : "=r"(r[0]), "=r"(r[1]) : "r"(addr));
}

__device__ __forceinline__ void mma_bf16(float c[4],
                                         uint32_t a0, uint32_t a1, uint32_t a2, uint32_t a3,
                                         uint32_t b0, uint32_t b1) {
    asm volatile("mma.sync.aligned.m16n8k16.row.col.f32.bf16.bf16.f32 "
                 "{%0,%1,%2,%3}, {%4,%5,%6,%7}, {%8,%9}, {%0,%1,%2,%3};"
                 : "+f"(c[0]), "+f"(c[1]), "+f"(c[2]), "+f"(c[3])
                 : "r"(a0), "r"(a1), "r"(a2), "r"(a3), "r"(b0), "r"(b1));
}

__device__ __forceinline__ uint32_t prmt(uint32_t a, uint32_t b, uint32_t sel) {
    uint32_t d;
    asm("prmt.b32 %0, %1, %2, %3;" : "=r"(d) : "r"(a), "r"(b), "r"(sel));
    return d;
}

// fast activations: explicit MUFU
__device__ __forceinline__ float ex2f(float x) { float y; asm("ex2.approx.ftz.f32 %0, %1;" : "=f"(y) : "f"(x)); return y; }
__device__ __forceinline__ float rcpf(float x) { float y; asm("rcp.approx.ftz.f32 %0, %1;" : "=f"(y) : "f"(x)); return y; }
#define LOG2E 1.4426950408889634f
__device__ __forceinline__ float sigm(float x) { return rcpf(1.0f + ex2f(-LOG2E * x)); }
__device__ __forceinline__ float tanh_fast(float x) { return 1.0f - 2.0f * rcpf(ex2f(2.0f * LOG2E * x) + 1.0f); }

__global__ void init_kernel() {
    int i = blockIdx.x * blockDim.x + threadIdx.x;
    for (; i < BATCH * UNITS; i += gridDim.x * blockDim.x) g_h[0][i] = 0u;
}

// ---------------- main persistent kernel ----------------
__global__ void __launch_bounds__(NTHREADS, 1) __cluster_dims__(CPG, 1, 1)
lstm_kernel(const int* __restrict__ tokens,
            const float* __restrict__ Wx,
            const float* __restrict__ Wh,
            const float* __restrict__ bias,
            const float* __restrict__ Wd,
            const float* __restrict__ bd,
            float* __restrict__ out) {
    extern __shared__ __align__(1024) char smem[];
    const uint32_t sb = smem_u32(smem);
    const int tid = threadIdx.x;
    const int w   = tid >> 5;            // warp 0..15
    const int L   = tid & 31;
    const int mg  = w & 3;               // m-group (32 A-rows)
    const int nq  = w >> 2;              // n-quarter (8 batch cols)
    const int group = blockIdx.x >> 3;
    const int r     = blockIdx.x & 7;
    const int gbase = group * MBATCH;

    float* wx_s = (float*)(smem + OFF_WX);

    // ---- prologue: W_h (fp32 -> bf16 hi/lo), Wx fp32 slice ----
    {
        const int m  = tid & 127;
        const int kh = tid >> 7;                  // quarter 0..3
        const int rw = m & 31;
        const int gate = rw >> 3;
        const int ulocal = (m >> 5) * 8 + (rw & 7);
        const int col = gate * 256 + r * UC + ulocal;
        for (int k = kh * 64; k < kh * 64 + 64; k++) {
            float wv = Wh[k * 1024 + col];
            __nv_bfloat16 hi = __float2bfloat16(wv);
            float rem = wv - __bfloat162float(hi);
            __nv_bfloat16 lo = __float2bfloat16(rem);
            uint32_t s = swz(m, k);
            *(__nv_bfloat16*)(smem + OFF_AHI + s) = hi;
            *(__nv_bfloat16*)(smem + OFF_ALO + s) = lo;
        }
        for (int ch = kh * 32; ch < kh * 32 + 32; ch++)
            wx_s[(gate * 32 + ulocal) * 130 + ch] = Wx[ch * 1024 + col];
    }

    // per-lane owned unit + bias regs
    const int ul = mg * 8 + (L >> 2);
    const float bi = bias[0 * 256 + r * UC + ul];
    const float bj = bias[1 * 256 + r * UC + ul];
    const float bf = bias[2 * 256 + r * UC + ul];
    const float bo = bias[3 * 256 + r * UC + ul];
    const float* wxi = &wx_s[(0 * 32 + ul) * 130];
    const float* wxj = &wx_s[(1 * 32 + ul) * 130];
    const float* wxf = &wx_s[(2 * 32 + ul) * 130];
    const float* wxo = &wx_s[(3 * 32 + ul) * 130];

    // ---- ldmatrix addresses ----
    const int rA   = (L & 7) + 8 * ((L >> 3) & 1);
    const uint32_t koffA = (L >> 4) ? 16u : 0u;
    const int rowA0 = mg * 32 + rA;
    const int rowA1 = rowA0 + 16;
    const uint32_t xA = ((uint32_t)rowA0 & 7u) << 4;
    const uint32_t aHi0 = sb + OFF_AHI + rowA0 * 512u;
    const uint32_t aHi1 = sb + OFF_AHI + rowA1 * 512u;
    const uint32_t aLo0 = sb + OFF_ALO + rowA0 * 512u;
    const uint32_t aLo1 = sb + OFF_ALO + rowA1 * 512u;
    // B (8n x 16k per k-step, ldsm.x2: lanes 0-7 k chunk 0, lanes 8-15 k+8)
    const int L16 = L & 15;
    const int rB = L16 & 7;
    const uint32_t koffB = ((L16 >> 3) & 1) ? 16u : 0u;
    const int nB = nq * 8 + rB;
    const uint32_t xB = ((uint32_t)rB & 7u) << 4;
    const uint32_t bHi = sb + OFF_BHI + nB * 512u;
    const uint32_t bLo = sb + OFF_BLO + nB * 512u;

    // per-lane batch columns + precomputed global h indices: bb(j) = nq*8 + (L&3)*2 + j
    int gidx[2], brow[2];
#pragma unroll
    for (int j = 0; j < 2; j++) {
        int bb = nq * 8 + (L & 3) * 2 + j;
        brow[j] = gbase + bb;
        gidx[j] = (gbase + bb) * UNITS + r * UC + ul;
    }

    // precomputed B-store swizzle offsets: idx4 = tid + ii*512, rows 32 x 64 uint4
    uint32_t soff[4];
#pragma unroll
    for (int ii = 0; ii < 4; ii++) {
        int idx4 = tid + (ii << 9);
        soff[ii] = swz(idx4 >> 6, (idx4 & 63) << 2);
    }

    float c_reg[2] = {0.0f, 0.0f};

    __syncthreads();

    // ---- A_hi m-tile0 register-stationary ----
    uint32_t AH0[16][4];
#pragma unroll
    for (int ks = 0; ks < 16; ks++) {
        const uint32_t ka = ((uint32_t)(ks * 32) + koffA) ^ xA;
        ldsm_x4(AH0[ks], aHi0 + ka);
    }

    CLUSTER_ARRIVE();

    // prefetch tokens + Wx gather for t=0 (barrier-skew shadow)
    float wvi[2], wvj[2], wvf[2], wvo[2];
#pragma unroll
    for (int e = 0; e < 2; e++) {
        int tk = __ldg(&tokens[brow[e] * SEQ + 0]);
        wvi[e] = wxi[tk]; wvj[e] = wxj[tk]; wvf[e] = wxf[tk]; wvo[e] = wxo[tk];
    }

    // ---- 1024 recurrent steps ----
    for (int t = 0; t < SEQ; t++) {
        CLUSTER_WAIT();   // all CTAs' h(t) stores visible; also CTA-wide barrier

        // fill B: 2048 uint4, 4 per thread; PRMT unpack into swizzled Bhi/Blo
        {
            const uint4* src = (const uint4*)&g_h[t & 1][gbase * UNITS];
#pragma unroll
            for (int ii = 0; ii < 4; ii++) {
                uint4 p = __ldcg(src + tid + (ii << 9));
                *(uint2*)(smem + OFF_BHI + soff[ii]) = make_uint2(prmt(p.x, p.y, 0x5410u), prmt(p.z, p.w, 0x5410u));
                *(uint2*)(smem + OFF_BLO + soff[ii]) = make_uint2(prmt(p.x, p.y, 0x7632u), prmt(p.z, p.w, 0x7632u));
            }
        }
        __syncthreads();

        // ---- MMA: gates = Whi*hhi + Whi*hlo + Wlo*hhi over K=256; A_hi tile0 resident ----
        float acc[2][4];
#pragma unroll
        for (int mt = 0; mt < 2; mt++)
#pragma unroll
            for (int e = 0; e < 4; e++) acc[mt][e] = 0.0f;

#pragma unroll
        for (int ks = 0; ks < 16; ks++) {
            const uint32_t ka = ((uint32_t)(ks * 32) + koffA) ^ xA;
            const uint32_t kb = ((uint32_t)(ks * 32) + koffB) ^ xB;
            uint32_t Ah1[4], Al0[4], Al1[4], Bh[2], Bl[2];
            ldsm_x2(Bh, bHi + kb);
            ldsm_x4(Ah1, aHi1 + ka);
            ldsm_x4(Al0, aLo0 + ka);
            ldsm_x4(Al1, aLo1 + ka);
            ldsm_x2(Bl, bLo + kb);
            mma_bf16(acc[0], AH0[ks][0], AH0[ks][1], AH0[ks][2], AH0[ks][3], Bh[0], Bh[1]);
            mma_bf16(acc[1], Ah1[0], Ah1[1], Ah1[2], Ah1[3], Bh[0], Bh[1]);
            mma_bf16(acc[0], Al0[0], Al0[1], Al0[2], Al0[3], Bh[0], Bh[1]);
            mma_bf16(acc[1], Al1[0], Al1[1], Al1[2], Al1[3], Bh[0], Bh[1]);
            mma_bf16(acc[0], AH0[ks][0], AH0[ks][1], AH0[ks][2], AH0[ks][3], Bl[0], Bl[1]);
            mma_bf16(acc[1], Ah1[0], Ah1[1], Ah1[2], Ah1[3], Bl[0], Bl[1]);
        }

        // ---- LSTM elementwise in registers (lane owns unit ul, 2 batch cols) ----
        // acc[0][j]=gate_i, acc[0][2+j]=gate_j, acc[1][j]=gate_f, acc[1][2+j]=gate_o
        {
            unsigned* dst = &g_h[(t + 1) & 1][0];
#pragma unroll
            for (int j = 0; j < 2; j++) {
                float gi = acc[0][j]     + wvi[j] + bi;
                float gj = acc[0][2 + j] + wvj[j] + bj;
                float gf = acc[1][j]     + wvf[j] + bf;
                float go = acc[1][2 + j] + wvo[j] + bo;
                float nc = c_reg[j] * sigm(gf + 1.0f) + sigm(gi) * tanh_fast(gj);
                c_reg[j] = nc;
                float nh2 = tanh_fast(nc) * sigm(go);
                __nv_bfloat16 hi = __float2bfloat16(nh2);
                float rem = nh2 - __bfloat162float(hi);
                __nv_bfloat16 lo = __float2bfloat16(rem);
                unsigned packed = (unsigned)__bfloat16_as_ushort(hi) | ((unsigned)__bfloat16_as_ushort(lo) << 16);
                __stcg(&dst[gidx[j]], packed);
            }
        }
        CLUSTER_ARRIVE();   // h(t+1) stores ordered (release)

        // prefetch next tokens + Wx in the skew shadow
        {
            const int tp = (t + 1 < SEQ) ? (t + 1) : (SEQ - 1);
#pragma unroll
            for (int e = 0; e < 2; e++) {
                int tk = __ldg(&tokens[brow[e] * SEQ + tp]);
                wvi[e] = wxi[tk]; wvj[e] = wxj[tk]; wvf[e] = wxf[tk]; wvo[e] = wxo[tk];
            }
        }
    }

    // ---- dense head: logits = h @ W_dense + b_dense (final h in g_h[0]) ----
    CLUSTER_WAIT();
    {
        float* hs = (float*)(smem + OFF_AHI);   // 4 rows x 256 fp32
        const int bstart = r * 4;
        for (int i = tid; i < 4 * UNITS; i += NTHREADS) {
            unsigned p = __ldcg(&g_h[0][(gbase + bstart + (i >> 8)) * UNITS + (i & 255)]);
            hs[i] = __bfloat162float(__ushort_as_bfloat16((unsigned short)(p & 0xFFFFu))) +
                    __bfloat162float(__ushort_as_bfloat16((unsigned short)(p >> 16)));
        }
        __syncthreads();
        const int n   = tid & 127;   // output char
        const int row = tid >> 7;    // batch row 0..3
        float a0 = bd[n];
        for (int k = 0; k < UNITS; k++)
            a0 += hs[row * 256 + k] * Wd[k * NUM_CHARS + n];
        out[(gbase + bstart + row) * NUM_CHARS + n] = a0;
    }
}

// ---------------- host launcher ----------------
extern "C" void kernel_launch(void* const* d_in, const int* in_sizes, int n_in,
                              void* d_out, int out_size) {
    (void)in_sizes; (void)n_in; (void)out_size;
    const int*   tokens = (const int*)d_in[0];
    const float* Wx     = (const float*)d_in[1];
    const float* Wh     = (const float*)d_in[2];
    const float* b      = (const float*)d_in[3];
    const float* Wd     = (const float*)d_in[4];
    const float* bdn    = (const float*)d_in[5];
    float* out = (float*)d_out;

    cudaFuncSetAttribute(lstm_kernel, cudaFuncAttributeMaxDynamicSharedMemorySize, SMEM_TOTAL);

    init_kernel<<<256, 256>>>();
    lstm_kernel<<<NCTAS, NTHREADS, SMEM_TOTAL>>>(tokens, Wx, Wh, b, Wd, bdn, out);
}